// round 3
// baseline (speedup 1.0000x reference)
#include <cuda_runtime.h>
#include <math.h>

#define NB 16
#define NH 32
#define NKVH 8
#define ND 128
#define NS 4096
#define NG 4
#define NSPLIT 32
#define CHUNK (NS / NSPLIT)   // 128
#define TILE 64
#define MAXPOS 4096
#define ATT_SCALE 0.08838834764831845f   // 1/sqrt(128)

// Static device scratch (no allocation allowed).
__device__ float  g_acc[(size_t)NB * NH * NSPLIT * ND];  // 8 MB
__device__ float  g_m[NB * NH * NSPLIT];
__device__ float  g_l[NB * NH * NSPLIT];
__device__ float4 g_rope[MAXPOS * 32];                   // 2 MB: (c0,c1,s0,s1) per (pos, lane)

// ---------------------------------------------------------------------------
// RoPE table: cos/sin for every possible position x lane-frequency-pair.
// ---------------------------------------------------------------------------
__global__ void rope_table_kernel()
{
    int idx  = blockIdx.x * blockDim.x + threadIdx.x;   // pos*32 + lane
    int lane = idx & 31;
    int pos  = idx >> 5;
    float inv0 = (float)exp(-9.210340371976184 * (double)(2 * lane)     / 64.0);
    float inv1 = (float)exp(-9.210340371976184 * (double)(2 * lane + 1) / 64.0);
    float s0, c0, s1, c1;
    sincosf((float)pos * inv0, &s0, &c0);
    sincosf((float)pos * inv1, &s1, &c1);
    g_rope[idx] = make_float4(c0, c1, s0, s1);
}

// ---------------------------------------------------------------------------
// Main split-KV kernel. CTA = (split, batch); warp = kv head.
// ---------------------------------------------------------------------------
__global__ __launch_bounds__(256, 2)
void pa_partial_kernel(const float* __restrict__ query,
                       const float* __restrict__ k_cache,
                       const float* __restrict__ v_cache,
                       const int*   __restrict__ slots,
                       const int*   __restrict__ positions,
                       const int*   __restrict__ ctx_lens)
{
    __shared__ float4 cs[TILE][32];          // rope factors per (key, lane): 32 KB
    __shared__ int    slot_sh[TILE];
    __shared__ float  score_sh[NKVH][TILE][4];  // scaled scores per (warp, key, head): 8 KB

    const int split = blockIdx.x;
    const int b     = blockIdx.y;
    const int tid   = threadIdx.x;
    const int w     = tid >> 5;       // warp = kv head
    const int lane  = tid & 31;

    const int ctx     = ctx_lens[b];
    const int s_begin = split * CHUNK;
    const int s_end   = min(ctx, s_begin + CHUNK);

    // ---- RoPE'd query (pos_last) from the table, 4 heads in registers ----
    float qlx[NG], qly[NG], qhx[NG], qhy[NG];
    {
        const int pos_last = positions[b * NS + ctx - 1];
        float4 cc = g_rope[pos_last * 32 + lane];
#pragma unroll
        for (int g = 0; g < NG; g++) {
            const float* qp = query + (size_t)(b * NH + w * NG + g) * ND;
            float2 a  = *(const float2*)(qp + 2 * lane);
            float2 bb = *(const float2*)(qp + 2 * lane + 64);
            qlx[g] = a.x * cc.x - bb.x * cc.z;
            qly[g] = a.y * cc.y - bb.y * cc.w;
            qhx[g] = bb.x * cc.x + a.x * cc.z;
            qhy[g] = bb.y * cc.y + a.y * cc.w;
        }
    }

    float  m[NG], l[NG];
    float4 acc[NG];
#pragma unroll
    for (int g = 0; g < NG; g++) {
        m[g] = -1e30f; l[g] = 0.f;
        acc[g] = make_float4(0.f, 0.f, 0.f, 0.f);
    }

    const float* kb = k_cache + w * ND;
    const float* vb = v_cache + w * ND;

    for (int t0 = s_begin; t0 < s_end; t0 += TILE) {
        const int n = min(TILE, s_end - t0);
        __syncthreads();   // previous tile fully consumed
        // Cooperative fill: slots + rope factors (coalesced table loads).
        if (tid < n) slot_sh[tid] = slots[b * NS + t0 + tid];
        for (int idx = tid; idx < n * 32; idx += 256) {
            int key = idx >> 5, ln = idx & 31;
            int pos = positions[b * NS + t0 + key];
            cs[key][ln] = g_rope[pos * 32 + ln];
        }
        __syncthreads();

        // ===== Pass A: scores (keys independent -> deep load pipelining) =====
        float tmax_local = -1e30f;   // running tile max for head (lane&3)
#pragma unroll 4
        for (int i = 0; i < n; i++) {
            int sl = slot_sh[i];
            const float* kr = kb + (size_t)sl * (NKVH * ND);
            float2 kA = *(const float2*)(kr + 2 * lane);
            float2 kB = *(const float2*)(kr + 2 * lane + 64);
            float4 cc = cs[i][lane];

            float r0 = kA.x * cc.x - kB.x * cc.z;
            float r1 = kA.y * cc.y - kB.y * cc.w;
            float r2 = kB.x * cc.x + kA.x * cc.z;
            float r3 = kB.y * cc.y + kA.y * cc.w;

            float d0 = qlx[0] * r0 + qly[0] * r1 + qhx[0] * r2 + qhy[0] * r3;
            float d1 = qlx[1] * r0 + qly[1] * r1 + qhx[1] * r2 + qhy[1] * r3;
            float d2 = qlx[2] * r0 + qly[2] * r1 + qhx[2] * r2 + qhy[2] * r3;
            float d3 = qlx[3] * r0 + qly[3] * r1 + qhx[3] * r2 + qhy[3] * r3;

            // Interleaved 4-value warp reduction: 6 shuffles total.
            // After it, lane l holds the COMPLETE dot of head (l & 3).
            float s1 = (lane & 1) ? d0 : d1;
            float e01 = ((lane & 1) ? d1 : d0) + __shfl_xor_sync(0xffffffffu, s1, 1);
            float s2 = (lane & 1) ? d2 : d3;
            float e23 = ((lane & 1) ? d3 : d2) + __shfl_xor_sync(0xffffffffu, s2, 1);
            float s3 = (lane & 2) ? e01 : e23;
            float f  = ((lane & 2) ? e23 : e01) + __shfl_xor_sync(0xffffffffu, s3, 2);
            f += __shfl_xor_sync(0xffffffffu, f, 4);
            f += __shfl_xor_sync(0xffffffffu, f, 8);
            f += __shfl_xor_sync(0xffffffffu, f, 16);

            f *= ATT_SCALE;
            tmax_local = fmaxf(tmax_local, f);
            if (lane < 4) score_sh[w][i][lane] = f;
        }
        __syncwarp();

        // ---- tile-level max update (once per tile, not per key) ----
        {
            float tm[NG];
#pragma unroll
            for (int g = 0; g < NG; g++)
                tm[g] = __shfl_sync(0xffffffffu, tmax_local, g);
#pragma unroll
            for (int g = 0; g < NG; g++) {
                float mn   = fmaxf(m[g], tm[g]);
                float corr = __expf(m[g] - mn);
                l[g] *= corr;
                acc[g].x *= corr; acc[g].y *= corr;
                acc[g].z *= corr; acc[g].w *= corr;
                m[g] = mn;
            }
        }

        // ===== Pass B: V accumulation (keys independent) =====
#pragma unroll 4
        for (int i = 0; i < n; i++) {
            int sl = slot_sh[i];
            float4 vv = *(const float4*)(vb + (size_t)sl * (NKVH * ND) + 4 * lane);
            float4 s  = *(const float4*)&score_sh[w][i][0];   // broadcast LDS
            float w0 = __expf(s.x - m[0]);
            float w1 = __expf(s.y - m[1]);
            float w2 = __expf(s.z - m[2]);
            float w3 = __expf(s.w - m[3]);
            l[0] += w0; l[1] += w1; l[2] += w2; l[3] += w3;
            acc[0].x = fmaf(w0, vv.x, acc[0].x); acc[0].y = fmaf(w0, vv.y, acc[0].y);
            acc[0].z = fmaf(w0, vv.z, acc[0].z); acc[0].w = fmaf(w0, vv.w, acc[0].w);
            acc[1].x = fmaf(w1, vv.x, acc[1].x); acc[1].y = fmaf(w1, vv.y, acc[1].y);
            acc[1].z = fmaf(w1, vv.z, acc[1].z); acc[1].w = fmaf(w1, vv.w, acc[1].w);
            acc[2].x = fmaf(w2, vv.x, acc[2].x); acc[2].y = fmaf(w2, vv.y, acc[2].y);
            acc[2].z = fmaf(w2, vv.z, acc[2].z); acc[2].w = fmaf(w2, vv.w, acc[2].w);
            acc[3].x = fmaf(w3, vv.x, acc[3].x); acc[3].y = fmaf(w3, vv.y, acc[3].y);
            acc[3].z = fmaf(w3, vv.z, acc[3].z); acc[3].w = fmaf(w3, vv.w, acc[3].w);
        }
    }

    // ---- write split partials ----
#pragma unroll
    for (int g = 0; g < NG; g++) {
        int h = w * NG + g;
        size_t p = (size_t)(b * NH + h) * NSPLIT + split;
        if (s_end > s_begin)
            *(float4*)(g_acc + p * ND + 4 * lane) = acc[g];
        if (lane == 0) { g_m[p] = m[g]; g_l[p] = l[g]; }
    }
}

// ---------------------------------------------------------------------------
// Combine: 512 threads/block; s-loop split 4 ways + smem reduce.
// ---------------------------------------------------------------------------
__global__ __launch_bounds__(512)
void pa_combine_kernel(float* __restrict__ out)
{
    __shared__ float osh[4][ND];

    const int bh  = blockIdx.x;          // b*NH + h
    const int tid = threadIdx.x;         // 0..511
    const int d   = tid & (ND - 1);
    const int j   = tid >> 7;            // 0..3: split-group

    const float* mrow = g_m + (size_t)bh * NSPLIT;
    const float* lrow = g_l + (size_t)bh * NSPLIT;

    float mv[NSPLIT];
    float M = -1e30f;
#pragma unroll
    for (int s = 0; s < NSPLIT; s++) { mv[s] = mrow[s]; M = fmaxf(M, mv[s]); }

    float L = 0.f;
#pragma unroll
    for (int s = 0; s < NSPLIT; s++) L += __expf(mv[s] - M) * lrow[s];

    float o = 0.f;
#pragma unroll
    for (int k = 0; k < NSPLIT / 4; k++) {
        int s = j * (NSPLIT / 4) + k;
        float f = __expf(mv[s] - M);
        o += f * g_acc[((size_t)bh * NSPLIT + s) * ND + d];
    }
    osh[j][d] = o;
    __syncthreads();
    if (j == 0)
        out[(size_t)bh * ND + d] =
            (osh[0][d] + osh[1][d] + osh[2][d] + osh[3][d]) / L;
}

extern "C" void kernel_launch(void* const* d_in, const int* in_sizes, int n_in,
                              void* d_out, int out_size)
{
    const float* query     = (const float*)d_in[0];
    const float* k_cache   = (const float*)d_in[1];
    const float* v_cache   = (const float*)d_in[2];
    const int*   slots     = (const int*)d_in[3];
    const int*   positions = (const int*)d_in[4];
    const int*   ctx_lens  = (const int*)d_in[5];
    float*       out       = (float*)d_out;

    rope_table_kernel<<<(MAXPOS * 32) / 256, 256>>>();
    dim3 grid(NSPLIT, NB);
    pa_partial_kernel<<<grid, 256>>>(query, k_cache, v_cache, slots, positions, ctx_lens);
    pa_combine_kernel<<<NB * NH, 512>>>(out);
}

// round 5
// speedup vs baseline: 1.3943x; 1.3943x over previous
#include <cuda_runtime.h>
#include <math.h>

#define NB 16
#define NH 32
#define NKVH 8
#define ND 128
#define NS 4096
#define NG 4
#define NSPLIT 32
#define CHUNK 128
#define TILE 128
#define ATT_SCALE 0.08838834764831845f   // 1/sqrt(128)

// Static device scratch (no allocation allowed).
__device__ float g_acc[(size_t)NB * NH * NSPLIT * ND];  // 8 MB
__device__ float g_m[NB * NH * NSPLIT];
__device__ float g_l[NB * NH * NSPLIT];
__device__ float g_invf[64];

// ---------------------------------------------------------------------------
// 64 inv_freq values, correctly rounded via fp64 — ONCE, 64 threads total.
// ---------------------------------------------------------------------------
__global__ void freq_kernel()
{
    int i = threadIdx.x;   // 0..63
    g_invf[i] = (float)exp(-9.210340371976184 * (double)i / 64.0);
}

__device__ __forceinline__ void process_key(
    float4 cc, float2 kA, float2 kB, float4 vv, int lane,
    const float* qlx, const float* qly, const float* qhx, const float* qhy,
    float* m, float* l, float4* acc)
{
    // RoPE on K (pairs are lane-local).
    float r0 = kA.x * cc.x - kB.x * cc.z;
    float r1 = kA.y * cc.y - kB.y * cc.w;
    float r2 = kB.x * cc.x + kA.x * cc.z;
    float r3 = kB.y * cc.y + kA.y * cc.w;

    float d0 = qlx[0] * r0 + qly[0] * r1 + qhx[0] * r2 + qhy[0] * r3;
    float d1 = qlx[1] * r0 + qly[1] * r1 + qhx[1] * r2 + qhy[1] * r3;
    float d2 = qlx[2] * r0 + qly[2] * r1 + qhx[2] * r2 + qhy[2] * r3;
    float d3 = qlx[3] * r0 + qly[3] * r1 + qhx[3] * r2 + qhy[3] * r3;

    // Interleaved reduction: fold 4 head-dots so lane l carries head (l&3),
    // then finish the warp sum. 6 shuffles instead of 20.
    float s1  = (lane & 1) ? d0 : d1;
    float e01 = ((lane & 1) ? d1 : d0) + __shfl_xor_sync(0xffffffffu, s1, 1);
    float s2  = (lane & 1) ? d2 : d3;
    float e23 = ((lane & 1) ? d3 : d2) + __shfl_xor_sync(0xffffffffu, s2, 1);
    float s3  = (lane & 2) ? e01 : e23;
    float f   = ((lane & 2) ? e23 : e01) + __shfl_xor_sync(0xffffffffu, s3, 2);
    f += __shfl_xor_sync(0xffffffffu, f, 4);
    f += __shfl_xor_sync(0xffffffffu, f, 8);
    f += __shfl_xor_sync(0xffffffffu, f, 16);
    // Lane g (g<4) now holds the complete dot of head g; broadcast.
    float d[NG];
#pragma unroll
    for (int g = 0; g < NG; g++)
        d[g] = __shfl_sync(0xffffffffu, f, g);

#pragma unroll
    for (int g = 0; g < NG; g++) {
        float sc = d[g];                // q already carries ATT_SCALE
        if (sc > m[g]) {                // warp-uniform, rare
            float corr = __expf(m[g] - sc);
            m[g] = sc;
            l[g] *= corr;
            acc[g].x *= corr; acc[g].y *= corr;
            acc[g].z *= corr; acc[g].w *= corr;
        }
        float wgt = __expf(sc - m[g]);
        l[g] += wgt;
        acc[g].x = fmaf(wgt, vv.x, acc[g].x);
        acc[g].y = fmaf(wgt, vv.y, acc[g].y);
        acc[g].z = fmaf(wgt, vv.z, acc[g].z);
        acc[g].w = fmaf(wgt, vv.w, acc[g].w);
    }
}

// ---------------------------------------------------------------------------
// Main split-KV kernel. CTA = (split, batch); warp = kv head.
// ---------------------------------------------------------------------------
__global__ __launch_bounds__(256, 2)
void pa_partial_kernel(const float* __restrict__ query,
                       const float* __restrict__ k_cache,
                       const float* __restrict__ v_cache,
                       const int*   __restrict__ slots,
                       const int*   __restrict__ positions,
                       const int*   __restrict__ ctx_lens)
{
    __shared__ float4 cs[TILE][32];   // rope factors: 64 KB
    __shared__ int    slot_sh[TILE];

    const int split = blockIdx.x;
    const int b     = blockIdx.y;
    const int tid   = threadIdx.x;
    const int w     = tid >> 5;       // warp = kv head
    const int lane  = tid & 31;

    const int ctx     = ctx_lens[b];
    const int s_begin = split * CHUNK;

    if (s_begin >= ctx) {             // empty split: mark and leave
        if (lane == 0) {
#pragma unroll
            for (int g = 0; g < NG; g++) {
                size_t p = (size_t)(b * NH + w * NG + g) * NSPLIT + split;
                g_m[p] = -1e30f; g_l[p] = 0.f;
            }
        }
        return;
    }
    const int n = min(ctx - s_begin, CHUNK);

    const float inv0 = g_invf[2 * lane];
    const float inv1 = g_invf[2 * lane + 1];

    // ---- cooperative fill: slots + rope factors (sincos once per (b,s)) ----
    if (tid < n) slot_sh[tid] = slots[b * NS + s_begin + tid];
    for (int key = w; key < n; key += 8) {
        float p = (float)positions[b * NS + s_begin + key];
        float fs0, fc0, fs1, fc1;
        sincosf(p * inv0, &fs0, &fc0);
        sincosf(p * inv1, &fs1, &fc1);
        cs[key][lane] = make_float4(fc0, fc1, fs0, fs1);
    }

    // ---- RoPE'd + pre-scaled query (4 heads) in registers ----
    float qlx[NG], qly[NG], qhx[NG], qhy[NG];
    {
        const int pos_last = positions[b * NS + ctx - 1];
        float sn0, cn0, sn1, cn1;
        sincosf((float)pos_last * inv0, &sn0, &cn0);
        sincosf((float)pos_last * inv1, &sn1, &cn1);
#pragma unroll
        for (int g = 0; g < NG; g++) {
            const float* qp = query + (size_t)(b * NH + w * NG + g) * ND;
            float2 a  = *(const float2*)(qp + 2 * lane);
            float2 bb = *(const float2*)(qp + 2 * lane + 64);
            qlx[g] = (a.x * cn0 - bb.x * sn0) * ATT_SCALE;
            qly[g] = (a.y * cn1 - bb.y * sn1) * ATT_SCALE;
            qhx[g] = (bb.x * cn0 + a.x * sn0) * ATT_SCALE;
            qhy[g] = (bb.y * cn1 + a.y * sn1) * ATT_SCALE;
        }
    }

    float  m[NG], l[NG];
    float4 acc[NG];
#pragma unroll
    for (int g = 0; g < NG; g++) {
        m[g] = -1e30f; l[g] = 0.f;
        acc[g] = make_float4(0.f, 0.f, 0.f, 0.f);
    }

    __syncthreads();

    const float* kb = k_cache + w * ND;
    const float* vb = v_cache + w * ND;

#define LOADK(j, KA, KB, VV)                                            \
    {                                                                   \
        int sl_ = slot_sh[(j)];                                         \
        const float* kr_ = kb + (size_t)sl_ * (NKVH * ND);              \
        const float* vr_ = vb + (size_t)sl_ * (NKVH * ND);              \
        KA = *(const float2*)(kr_ + 2 * lane);                          \
        KB = *(const float2*)(kr_ + 2 * lane + 64);                     \
        VV = *(const float4*)(vr_ + 4 * lane);                          \
    }

    // Depth-3 software pipeline: K/V for keys i+3..i+5 in flight.
    float2 kA0, kB0, kA1, kB1, kA2, kB2;
    float4 v0, v1, v2;
    LOADK(0, kA0, kB0, v0);
    LOADK(min(1, n - 1), kA1, kB1, v1);
    LOADK(min(2, n - 1), kA2, kB2, v2);

    for (int i = 0; i < n; i += 3) {
        {
            float2 ka = kA0, kk = kB0; float4 vv = v0;
            LOADK(min(i + 3, n - 1), kA0, kB0, v0);
            process_key(cs[i][lane], ka, kk, vv, lane, qlx, qly, qhx, qhy, m, l, acc);
        }
        if (i + 1 < n) {
            float2 ka = kA1, kk = kB1; float4 vv = v1;
            LOADK(min(i + 4, n - 1), kA1, kB1, v1);
            process_key(cs[i + 1][lane], ka, kk, vv, lane, qlx, qly, qhx, qhy, m, l, acc);
        }
        if (i + 2 < n) {
            float2 ka = kA2, kk = kB2; float4 vv = v2;
            LOADK(min(i + 5, n - 1), kA2, kB2, v2);
            process_key(cs[i + 2][lane], ka, kk, vv, lane, qlx, qly, qhx, qhy, m, l, acc);
        }
    }
#undef LOADK

    // ---- write split partials ----
#pragma unroll
    for (int g = 0; g < NG; g++) {
        size_t p = (size_t)(b * NH + w * NG + g) * NSPLIT + split;
        *(float4*)(g_acc + p * ND + 4 * lane) = acc[g];
        if (lane == 0) { g_m[p] = m[g]; g_l[p] = l[g]; }
    }
}

// ---------------------------------------------------------------------------
// Combine: 512 threads/block; s-loop split 4 ways + smem reduce.
// ---------------------------------------------------------------------------
__global__ __launch_bounds__(512)
void pa_combine_kernel(float* __restrict__ out)
{
    __shared__ float osh[4][ND];

    const int bh  = blockIdx.x;          // b*NH + h
    const int tid = threadIdx.x;
    const int d   = tid & (ND - 1);
    const int j   = tid >> 7;            // 0..3

    const float* mrow = g_m + (size_t)bh * NSPLIT;
    const float* lrow = g_l + (size_t)bh * NSPLIT;

    float mv[NSPLIT];
    float M = -1e30f;
#pragma unroll
    for (int s = 0; s < NSPLIT; s++) { mv[s] = mrow[s]; M = fmaxf(M, mv[s]); }

    float L = 0.f;
#pragma unroll
    for (int s = 0; s < NSPLIT; s++) L += __expf(mv[s] - M) * lrow[s];

    float o = 0.f;
#pragma unroll
    for (int k = 0; k < NSPLIT / 4; k++) {
        int s = j * (NSPLIT / 4) + k;
        float f = __expf(mv[s] - M);     // exactly 0 for empty splits
        o += f * g_acc[((size_t)bh * NSPLIT + s) * ND + d];
    }
    osh[j][d] = o;
    __syncthreads();
    if (j == 0)
        out[(size_t)bh * ND + d] =
            (osh[0][d] + osh[1][d] + osh[2][d] + osh[3][d]) / L;
}

extern "C" void kernel_launch(void* const* d_in, const int* in_sizes, int n_in,
                              void* d_out, int out_size)
{
    const float* query     = (const float*)d_in[0];
    const float* k_cache   = (const float*)d_in[1];
    const float* v_cache   = (const float*)d_in[2];
    const int*   slots     = (const int*)d_in[3];
    const int*   positions = (const int*)d_in[4];
    const int*   ctx_lens  = (const int*)d_in[5];
    float*       out       = (float*)d_out;

    freq_kernel<<<1, 64>>>();
    dim3 grid(NSPLIT, NB);
    pa_partial_kernel<<<grid, 256>>>(query, k_cache, v_cache, slots, positions, ctx_lens);
    pa_combine_kernel<<<NB * NH, 512>>>(out);
}